// round 12
// baseline (speedup 1.0000x reference)
#include <cuda_runtime.h>
#include <stdint.h>

// Fixed problem shape (LengthRegulator_33285996544559):
//   x:   [B=32, T=512, C=512] float32
//   dur: [B=32, T=512] int32 in [0, 12)
//   out: [B, T_out, C] float32, T_out = out_size / (B*C)
#define B_DIM 32
#define T_DIM 512
#define C_DIM 512
#define MAX_TOUT (T_DIM * 11)   // dur <= 11 -> cumsum <= 5632

// Scratch: per-(b, t_out) source index. ~720 KB static device global.
__device__ int g_idx[B_DIM * MAX_TOUT];

// Kernel 1: shfl-based inclusive scan of the row's 512 durations, then
// scatter expansion (each token writes its own output range, <= 11 ints)
// plus tail fill with T-1. One block per row, 512 threads, 3 syncthreads.
__global__ void __launch_bounds__(512) build_idx_kernel(
    const int* __restrict__ dur, int t_out)
{
    __shared__ int s_wsum[16];

    const int row  = blockIdx.x;
    const int tid  = threadIdx.x;
    const int wid  = tid >> 5;
    const int lane = tid & 31;

    int d = dur[row * T_DIM + tid];
    if (d < 0) d = 0;

    int v = d;
    #pragma unroll
    for (int off = 1; off < 32; off <<= 1) {
        int n = __shfl_up_sync(0xffffffffu, v, off);
        if (lane >= off) v += n;
    }
    if (lane == 31) s_wsum[wid] = v;
    __syncthreads();
    if (wid == 0) {
        int w = (lane < 16) ? s_wsum[lane] : 0;
        #pragma unroll
        for (int off = 1; off < 16; off <<= 1) {
            int n = __shfl_up_sync(0xffffffffu, w, off);
            if (lane >= off) w += n;
        }
        if (lane < 16) s_wsum[lane] = w;
    }
    __syncthreads();

    const int incl  = ((wid > 0) ? s_wsum[wid - 1] : 0) + v;
    const int excl  = incl - d;
    const int total = s_wsum[15];

    int* rowp = g_idx + row * t_out;
    for (int t = excl; t < incl; t++) rowp[t] = tid;
    for (int t = total + tid; t < t_out; t += T_DIM) rowp[t] = T_DIM - 1;

#if __CUDA_ARCH__ >= 900
    cudaTriggerProgrammaticLaunchCompletion();
#endif
}

// Kernel 2: proven R3 gather (35.97us steady-state): one warp per TWO output
// frames, all 8 LDG.128 issued before any store (MLP=8/thread), __stcs
// streaming stores. Launched via PDL: starts while build_idx drains, does
// idx-independent setup, then grid-dependency-syncs before reading g_idx.
__global__ void __launch_bounds__(256) gather_kernel(
    const float4* __restrict__ x4,
    float4*       __restrict__ out4,
    int t_out, int n_frames)
{
    int w    = (blockIdx.x * blockDim.x + threadIdx.x) >> 5;
    int lane = threadIdx.x & 31;
    int f0   = w << 1;

    // idx-independent setup (overlaps predecessor)
    bool active = f0 < n_frames;
    bool has2   = (f0 + 1) < n_frames;
    int  f1     = has2 ? (f0 + 1) : f0;
    int  b0 = 0, b1 = 0;
    if (active) { b0 = f0 / t_out; b1 = f1 / t_out; }

#if __CUDA_ARCH__ >= 900
    cudaGridDependencySynchronize();
#endif
    if (!active) return;

    int i0 = __ldg(&g_idx[f0]);
    int i1 = __ldg(&g_idx[f1]);

    const float4* s0 = x4 + ((long long)(b0 * T_DIM + i0) << 7);
    const float4* s1 = x4 + ((long long)(b1 * T_DIM + i1) << 7);

    float4 v0 = __ldg(&s0[lane]);
    float4 v1 = __ldg(&s0[lane + 32]);
    float4 v2 = __ldg(&s0[lane + 64]);
    float4 v3 = __ldg(&s0[lane + 96]);
    float4 u0 = __ldg(&s1[lane]);
    float4 u1 = __ldg(&s1[lane + 32]);
    float4 u2 = __ldg(&s1[lane + 64]);
    float4 u3 = __ldg(&s1[lane + 96]);

    float4* d0 = out4 + ((long long)f0 << 7);
    __stcs(&d0[lane],      v0);
    __stcs(&d0[lane + 32], v1);
    __stcs(&d0[lane + 64], v2);
    __stcs(&d0[lane + 96], v3);

    if (has2) {
        float4* d1 = out4 + ((long long)f1 << 7);
        __stcs(&d1[lane],      u0);
        __stcs(&d1[lane + 32], u1);
        __stcs(&d1[lane + 64], u2);
        __stcs(&d1[lane + 96], u3);
    }
}

extern "C" void kernel_launch(void* const* d_in, const int* in_sizes, int n_in,
                              void* d_out, int out_size) {
    const float* x   = (const float*)d_in[0];
    const int*   dur = (const int*)d_in[1];
    float*       out = (float*)d_out;

    const int t_out    = out_size / (B_DIM * C_DIM);
    const int n_frames = B_DIM * t_out;

    build_idx_kernel<<<B_DIM, T_DIM>>>(dur, t_out);

    const int threads = 256;                // 8 warps -> 16 frames / block
    int n_warps = (n_frames + 1) >> 1;
    int blocks  = (n_warps * 32 + threads - 1) / threads;

    // Programmatic dependent launch: gather begins while build_idx drains;
    // cudaGridDependencySynchronize() in-kernel enforces the data dependency.
    cudaLaunchConfig_t cfg = {};
    cfg.gridDim  = dim3((unsigned)blocks);
    cfg.blockDim = dim3(threads);
    cudaLaunchAttribute attr[1];
    attr[0].id = cudaLaunchAttributeProgrammaticStreamSerialization;
    attr[0].val.programmaticStreamSerializationAllowed = 1;
    cfg.attrs    = attr;
    cfg.numAttrs = 1;

    cudaLaunchKernelEx(&cfg, gather_kernel,
                       (const float4*)x, (float4*)out, t_out, n_frames);
}